// round 9
// baseline (speedup 1.0000x reference)
#include <cuda_runtime.h>
#include <cuda_fp16.h>
#include <cstdint>
#include <math.h>

#define NN 100000
#define NE 1600000
#define NG 512
#define NB_SCAN 196   // ceil(NN/512)

// ---------------- device scratch (static, no allocations) ----------------
__device__ __align__(16) __half g_H[NN * 128];   // ping
__device__ __align__(16) __half g_X[NN * 128];   // pong
__device__ __align__(16) __half g_W2[16384], g_W3[16384], g_W4[8192];
__device__ int   g_ideg[NN];
__device__ float g_dinv[NN];
__device__ __align__(16) int   g_csrc[NE];
__device__ __align__(16) float g_cnorm[NE];
__device__ int   g_rowptr[NN + 1];
__device__ int   g_cur[NN];
__device__ int   g_bsum[256];
__device__ __align__(16) float g_pool[NG * 64];
__device__ float g_cnt[NG];
__device__ int   g_e32;
__device__ int   g_b32;

// ---------------- helpers ----------------
__device__ __forceinline__ void red_add_v4(float* p, float a, float b, float c, float d) {
    asm volatile("red.global.add.v4.f32 [%0], {%1,%2,%3,%4};"
                 :: "l"(p), "f"(a), "f"(b), "f"(c), "f"(d) : "memory");
}
__device__ __forceinline__ uint32_t sptr(const void* p) {
    return (uint32_t)__cvta_generic_to_shared(p);
}
__device__ __forceinline__ void cp16(uint32_t dst, const void* src, bool valid) {
    int b = valid ? 16 : 0;
    asm volatile("cp.async.cg.shared.global [%0], [%1], 16, %2;"
                 :: "r"(dst), "l"(src), "r"(b));
}
__device__ __forceinline__ void cp_commit() {
    asm volatile("cp.async.commit_group;");
}
template<int N>
__device__ __forceinline__ void cp_wait() {
    asm volatile("cp.async.wait_group %0;" :: "n"(N));
}
__device__ __forceinline__ void ldsm_x4(uint32_t (&r)[4], uint32_t a) {
    asm volatile("ldmatrix.sync.aligned.m8n8.x4.shared.b16 {%0,%1,%2,%3}, [%4];"
                 : "=r"(r[0]), "=r"(r[1]), "=r"(r[2]), "=r"(r[3]) : "r"(a));
}
__device__ __forceinline__ void ldsm_x2t(uint32_t (&r)[2], uint32_t a) {
    asm volatile("ldmatrix.sync.aligned.m8n8.x2.trans.shared.b16 {%0,%1}, [%2];"
                 : "=r"(r[0]), "=r"(r[1]) : "r"(a));
}
__device__ __forceinline__ void mma_f16(float (&d)[4], const uint32_t (&a)[4],
                                        const uint32_t (&b)[2]) {
    asm volatile("mma.sync.aligned.m16n8k16.row.col.f32.f16.f16.f32 "
                 "{%0,%1,%2,%3}, {%4,%5,%6,%7}, {%8,%9}, {%0,%1,%2,%3};"
                 : "+f"(d[0]), "+f"(d[1]), "+f"(d[2]), "+f"(d[3])
                 : "r"(a[0]), "r"(a[1]), "r"(a[2]), "r"(a[3]), "r"(b[0]), "r"(b[1]));
}
__device__ __forceinline__ void acc_h4(float4& acc, uint2 u, float n) {
    float2 a = __half22float2(*(__half2*)&u.x);
    float2 b = __half22float2(*(__half2*)&u.y);
    acc.x += n * a.x; acc.y += n * a.y; acc.z += n * b.x; acc.w += n * b.y;
}

// X smem stride (128 data + 8 pad halves)
#define XSS 136

// GEMM from smem tiles: Hout[row0..row0+128) = sX(128x128) @ sW(128xDOUT)
template<int DOUT>
__device__ __forceinline__ void gemm_smem(const __half* sX, const __half* sW,
                                          __half* __restrict__ Hout, int row0, int tid) {
    constexpr int WS = DOUT + 8;
    constexpr int NW = DOUT / 2;
    constexpr int NF = NW / 8;
    const int wid = tid >> 5;
    const int lane = tid & 31;
    const int warpM = wid & 3;
    const int warpN = wid >> 2;

    float acc[2][NF][4];
    #pragma unroll
    for (int mi = 0; mi < 2; mi++)
        #pragma unroll
        for (int ni = 0; ni < NF; ni++)
            acc[mi][ni][0] = acc[mi][ni][1] = acc[mi][ni][2] = acc[mi][ni][3] = 0.f;

    #pragma unroll
    for (int kk = 0; kk < 128; kk += 16) {
        uint32_t a[2][4], b[NF][2];
        #pragma unroll
        for (int mi = 0; mi < 2; mi++) {
            int r = warpM * 32 + mi * 16 + (lane & 15);
            int c = kk + ((lane >> 4) << 3);
            ldsm_x4(a[mi], sptr(sX + r * XSS + c));
        }
        #pragma unroll
        for (int ni = 0; ni < NF; ni++) {
            int r = kk + (lane & 15);
            int c = warpN * NW + ni * 8;
            ldsm_x2t(b[ni], sptr(sW + r * WS + c));
        }
        #pragma unroll
        for (int mi = 0; mi < 2; mi++)
            #pragma unroll
            for (int ni = 0; ni < NF; ni++)
                mma_f16(acc[mi][ni], a[mi], b[ni]);
    }

    #pragma unroll
    for (int mi = 0; mi < 2; mi++) {
        int r0 = row0 + warpM * 32 + mi * 16 + (lane >> 2);
        int c0 = warpN * NW + (lane & 3) * 2;
        #pragma unroll
        for (int ni = 0; ni < NF; ni++) {
            int c = c0 + ni * 8;
            if (r0 < NN) {
                __half2 h = __floats2half2_rn(acc[mi][ni][0], acc[mi][ni][1]);
                *(__half2*)(Hout + (size_t)r0 * DOUT + c) = h;
            }
            if (r0 + 8 < NN) {
                __half2 h = __floats2half2_rn(acc[mi][ni][2], acc[mi][ni][3]);
                *(__half2*)(Hout + (size_t)(r0 + 8) * DOUT + c) = h;
            }
        }
    }
}

// ---------------- dtype detection (int32 vs int64 index arrays) ----------
__global__ void k_detect(const unsigned* __restrict__ e, const unsigned* __restrict__ b) {
    __shared__ unsigned se[256], sb[256];
    int t = threadIdx.x;
    unsigned ae = 0, ab = 0;
    const int SE = (2 * NE) / 4096;
    const int SB = NN / 4096;
    for (int i = t; i < 4096; i += 256) {
        ae |= e[(i * SE) | 1];
        ab |= b[(i * SB) | 1];
    }
    se[t] = ae; sb[t] = ab;
    __syncthreads();
    for (int s = 128; s; s >>= 1) {
        if (t < s) { se[t] |= se[t + s]; sb[t] |= sb[t + s]; }
        __syncthreads();
    }
    if (t == 0) { g_e32 = (se[0] != 0); g_b32 = (sb[0] != 0); }
}

// zero counters + convert weights (merged; independent work)
__global__ void k_init(const float* __restrict__ W2, const float* __restrict__ W3,
                       const float* __restrict__ W4) {
    int i = blockIdx.x * blockDim.x + threadIdx.x;
    if (i < NN) g_ideg[i] = 0;
    if (i < NG * 64) g_pool[i] = 0.0f;
    if (i < NG) g_cnt[i] = 0.0f;
    if (i < 16384)      g_W2[i] = __float2half_rn(W2[i]);
    else if (i < 32768) g_W3[i - 16384] = __float2half_rn(W3[i - 16384]);
    else if (i < 40960) g_W4[i - 32768] = __float2half_rn(W4[i - 32768]);
}

__global__ void k_deg(const void* __restrict__ ei) {
    int e = blockIdx.x * blockDim.x + threadIdx.x;
    if (e >= NE) return;
    int d;
    if (g_e32) d = ((const int*)ei)[NE + e];
    else       d = (int)((const long long*)ei)[NE + e];
    atomicAdd(&g_ideg[d], 1);
}

// ---------------- 2-level exclusive scan of degrees -> rowptr ------------
__global__ void k_scan1() {
    __shared__ int sm[512];
    int t = threadIdx.x;
    int i = blockIdx.x * 512 + t;
    int v = (i < NN) ? g_ideg[i] : 0;
    sm[t] = v;
    __syncthreads();
    for (int off = 1; off < 512; off <<= 1) {
        int x = 0;
        if (t >= off) x = sm[t - off];
        __syncthreads();
        if (t >= off) sm[t] += x;
        __syncthreads();
    }
    if (i < NN) g_rowptr[i] = sm[t] - v;
    if (t == 511) g_bsum[blockIdx.x] = sm[511];
}

__global__ void k_scan2() {
    __shared__ int sm[256];
    int t = threadIdx.x;
    int v = (t < NB_SCAN) ? g_bsum[t] : 0;
    sm[t] = v;
    __syncthreads();
    for (int off = 1; off < 256; off <<= 1) {
        int x = 0;
        if (t >= off) x = sm[t - off];
        __syncthreads();
        if (t >= off) sm[t] += x;
        __syncthreads();
    }
    if (t < NB_SCAN) g_bsum[t] = sm[t] - v;
}

__global__ void k_scan3() {
    int i = blockIdx.x * blockDim.x + threadIdx.x;
    if (i < NN) {
        int r = g_rowptr[i] + g_bsum[i >> 9];
        g_rowptr[i] = r;
        g_cur[i] = r;
        g_dinv[i] = rsqrtf((float)g_ideg[i] + 1.0f);
    }
    if (i == 0) g_rowptr[NN] = NE;
}

__global__ void k_build(const void* __restrict__ ei) {
    int e = blockIdx.x * blockDim.x + threadIdx.x;
    if (e >= NE) return;
    int s, d;
    if (g_e32) {
        const int* p = (const int*)ei;
        s = p[e]; d = p[NE + e];
    } else {
        const long long* p = (const long long*)ei;
        s = (int)p[e]; d = (int)p[NE + e];
    }
    int pos = atomicAdd(&g_cur[d], 1);
    g_csrc[pos] = s;
    g_cnorm[pos] = g_dinv[s] * g_dinv[d];
}

// ---------------- fused layer 1: agg3 + (3->128 GEMM) + (128x128 TC GEMM) -
// Per block: 128 rows. A = Â x (dim 3); X2 = relu(A@W1+b1) -> smem; H2 = X2@W2.
__global__ __launch_bounds__(256) void k_layer1(
    const float* __restrict__ x, const float* __restrict__ W1,
    const float* __restrict__ b1, const __half* __restrict__ W2h,
    __half* __restrict__ Hout) {
    extern __shared__ __half smem[];
    __half* sX = smem;                       // 128*136
    __half* sW = sX + 128 * XSS;             // 128*136
    float* sW1 = (float*)(sW + 128 * XSS);   // 384
    float* sb1 = sW1 + 384;                  // 128

    const int tid = threadIdx.x;
    const int row0 = blockIdx.x * 128;

    // async load W2 tile
    for (int i = tid; i < 128 * 16; i += 256) {
        int r = i >> 4, c = (i & 15) * 8;
        cp16(sptr(sW + r * XSS + c), W2h + (size_t)r * 128 + c, true);
    }
    cp_commit();

    // stage W1 + b1
    for (int i = tid; i < 384; i += 256) sW1[i] = W1[i];
    if (tid < 128) sb1[tid] = b1[tid];

    // agg3: 2 threads per row
    int r = tid >> 1, j = tid & 1;
    int d = row0 + r;
    float a0 = 0.f, a1 = 0.f, a2 = 0.f;
    if (d < NN) {
        int p = g_rowptr[d] + j, pe = g_rowptr[d + 1];
        for (; p < pe; p += 2) {
            int s = g_csrc[p]; float nm = g_cnorm[p];
            a0 += nm * x[s * 3]; a1 += nm * x[s * 3 + 1]; a2 += nm * x[s * 3 + 2];
        }
        if (j == 0) {
            float dv = g_dinv[d], sl = dv * dv;
            a0 += sl * x[d * 3]; a1 += sl * x[d * 3 + 1]; a2 += sl * x[d * 3 + 2];
        }
    }
    a0 += __shfl_xor_sync(0xFFFFFFFFu, a0, 1);
    a1 += __shfl_xor_sync(0xFFFFFFFFu, a1, 1);
    a2 += __shfl_xor_sync(0xFFFFFFFFu, a2, 1);
    __syncthreads();   // sW1/sb1 visible

    // gemm3: each thread computes 64 cols of its row -> smem (zeros if OOB)
    for (int c = j * 64; c < j * 64 + 64; c += 4) {
        uint2 o = make_uint2(0, 0);
        if (d < NN) {
            float h0 = fmaxf(a0 * sW1[c]     + a1 * sW1[128 + c]     + a2 * sW1[256 + c]     + sb1[c],     0.f);
            float h1 = fmaxf(a0 * sW1[c + 1] + a1 * sW1[128 + c + 1] + a2 * sW1[256 + c + 1] + sb1[c + 1], 0.f);
            float h2 = fmaxf(a0 * sW1[c + 2] + a1 * sW1[128 + c + 2] + a2 * sW1[256 + c + 2] + sb1[c + 2], 0.f);
            float h3 = fmaxf(a0 * sW1[c + 3] + a1 * sW1[128 + c + 3] + a2 * sW1[256 + c + 3] + sb1[c + 3], 0.f);
            *(__half2*)&o.x = __floats2half2_rn(h0, h1);
            *(__half2*)&o.y = __floats2half2_rn(h2, h3);
        }
        *(uint2*)(sX + r * XSS + c) = o;
    }
    cp_wait<0>();
    __syncthreads();

    gemm_smem<128>(sX, sW, Hout, row0, tid);
}

// ---------------- fused: X' = relu(Â Hin + b) (smem) ; Hout = X' @ W -------
template<int DOUT>
__global__ __launch_bounds__(256) void k_agg_gemm(
    const __half* __restrict__ Hin, const float* __restrict__ Bias,
    const __half* __restrict__ W, __half* __restrict__ Hout) {
    constexpr int WS = DOUT + 8;
    constexpr int WU4 = DOUT / 8;
    extern __shared__ __half smem[];
    __half* sX = smem;              // 128*136
    __half* sW = sX + 128 * XSS;    // 128*WS

    const int tid = threadIdx.x;
    const int wid = tid >> 5;
    const int lane = tid & 31;
    const int row0 = blockIdx.x * 128;

    // async load W tile
    for (int i = tid; i < 128 * WU4; i += 256) {
        int r = i / WU4, c = (i % WU4) * 8;
        cp16(sptr(sW + r * WS + c), W + (size_t)r * DOUT + c, true);
    }
    cp_commit();

    // agg phase: warp wid handles rows row0 + wid*16 .. +15
    const uint2* H2 = (const uint2*)Hin;
    float4 bv = ((const float4*)Bias)[lane];
    for (int i = 0; i < 16; i++) {
        int r = wid * 16 + i;
        int d = row0 + r;
        uint2 o = make_uint2(0, 0);
        if (d < NN) {
            int p = g_rowptr[d], pe = g_rowptr[d + 1];
            float4 acc = make_float4(0.f, 0.f, 0.f, 0.f);
            while (p < pe && (p & 3)) {
                acc_h4(acc, H2[(size_t)g_csrc[p] * 32 + lane], g_cnorm[p]);
                p++;
            }
            for (; p + 8 <= pe; p += 8) {
                int4   i0 = *(const int4*)&g_csrc[p];
                int4   i1 = *(const int4*)&g_csrc[p + 4];
                float4 n0 = *(const float4*)&g_cnorm[p];
                float4 n1 = *(const float4*)&g_cnorm[p + 4];
                uint2 u0 = H2[(size_t)i0.x * 32 + lane];
                uint2 u1 = H2[(size_t)i0.y * 32 + lane];
                uint2 u2 = H2[(size_t)i0.z * 32 + lane];
                uint2 u3 = H2[(size_t)i0.w * 32 + lane];
                uint2 u4 = H2[(size_t)i1.x * 32 + lane];
                uint2 u5 = H2[(size_t)i1.y * 32 + lane];
                uint2 u6 = H2[(size_t)i1.z * 32 + lane];
                uint2 u7 = H2[(size_t)i1.w * 32 + lane];
                acc_h4(acc, u0, n0.x); acc_h4(acc, u1, n0.y);
                acc_h4(acc, u2, n0.z); acc_h4(acc, u3, n0.w);
                acc_h4(acc, u4, n1.x); acc_h4(acc, u5, n1.y);
                acc_h4(acc, u6, n1.z); acc_h4(acc, u7, n1.w);
            }
            if (p + 4 <= pe) {
                int4   i0 = *(const int4*)&g_csrc[p];
                float4 n0 = *(const float4*)&g_cnorm[p];
                uint2 u0 = H2[(size_t)i0.x * 32 + lane];
                uint2 u1 = H2[(size_t)i0.y * 32 + lane];
                uint2 u2 = H2[(size_t)i0.z * 32 + lane];
                uint2 u3 = H2[(size_t)i0.w * 32 + lane];
                acc_h4(acc, u0, n0.x); acc_h4(acc, u1, n0.y);
                acc_h4(acc, u2, n0.z); acc_h4(acc, u3, n0.w);
                p += 4;
            }
            for (; p < pe; p++)
                acc_h4(acc, H2[(size_t)g_csrc[p] * 32 + lane], g_cnorm[p]);

            float dv = g_dinv[d], sl = dv * dv;
            acc_h4(acc, H2[(size_t)d * 32 + lane], sl);
            acc.x = fmaxf(acc.x + bv.x, 0.f);
            acc.y = fmaxf(acc.y + bv.y, 0.f);
            acc.z = fmaxf(acc.z + bv.z, 0.f);
            acc.w = fmaxf(acc.w + bv.w, 0.f);
            *(__half2*)&o.x = __floats2half2_rn(acc.x, acc.y);
            *(__half2*)&o.y = __floats2half2_rn(acc.z, acc.w);
        }
        *(uint2*)(sX + r * XSS + lane * 4) = o;
    }
    cp_wait<0>();
    __syncthreads();

    gemm_smem<DOUT>(sX, sW, Hout, row0, tid);
}

// ---------------- final agg (dim 64, fp16 gather) + mean-pool scatter ----
__global__ void k_agg64_pool(const __half* __restrict__ H, const float* __restrict__ B,
                             const void* __restrict__ batch) {
    int gt = blockIdx.x * blockDim.x + threadIdx.x;
    int d = gt >> 4;
    int c = gt & 15;
    if (d >= NN) return;
    const uint2* H2 = (const uint2*)H;
    int p = g_rowptr[d], pe = g_rowptr[d + 1];
    float4 acc = make_float4(0.f, 0.f, 0.f, 0.f);
    while (p < pe && (p & 3)) {
        acc_h4(acc, H2[(size_t)g_csrc[p] * 16 + c], g_cnorm[p]);
        p++;
    }
    for (; p + 8 <= pe; p += 8) {
        int4   i0 = *(const int4*)&g_csrc[p];
        int4   i1 = *(const int4*)&g_csrc[p + 4];
        float4 n0 = *(const float4*)&g_cnorm[p];
        float4 n1 = *(const float4*)&g_cnorm[p + 4];
        uint2 u0 = H2[(size_t)i0.x * 16 + c];
        uint2 u1 = H2[(size_t)i0.y * 16 + c];
        uint2 u2 = H2[(size_t)i0.z * 16 + c];
        uint2 u3 = H2[(size_t)i0.w * 16 + c];
        uint2 u4 = H2[(size_t)i1.x * 16 + c];
        uint2 u5 = H2[(size_t)i1.y * 16 + c];
        uint2 u6 = H2[(size_t)i1.z * 16 + c];
        uint2 u7 = H2[(size_t)i1.w * 16 + c];
        acc_h4(acc, u0, n0.x); acc_h4(acc, u1, n0.y);
        acc_h4(acc, u2, n0.z); acc_h4(acc, u3, n0.w);
        acc_h4(acc, u4, n1.x); acc_h4(acc, u5, n1.y);
        acc_h4(acc, u6, n1.z); acc_h4(acc, u7, n1.w);
    }
    if (p + 4 <= pe) {
        int4   i0 = *(const int4*)&g_csrc[p];
        float4 n0 = *(const float4*)&g_cnorm[p];
        uint2 u0 = H2[(size_t)i0.x * 16 + c];
        uint2 u1 = H2[(size_t)i0.y * 16 + c];
        uint2 u2 = H2[(size_t)i0.z * 16 + c];
        uint2 u3 = H2[(size_t)i0.w * 16 + c];
        acc_h4(acc, u0, n0.x); acc_h4(acc, u1, n0.y);
        acc_h4(acc, u2, n0.z); acc_h4(acc, u3, n0.w);
        p += 4;
    }
    for (; p < pe; p++)
        acc_h4(acc, H2[(size_t)g_csrc[p] * 16 + c], g_cnorm[p]);

    float dv = g_dinv[d], sl = dv * dv;
    acc_h4(acc, H2[(size_t)d * 16 + c], sl);
    float4 bv = ((const float4*)B)[c];
    acc.x += bv.x; acc.y += bv.y; acc.z += bv.z; acc.w += bv.w;
    int g;
    if (g_b32) g = ((const int*)batch)[d];
    else       g = (int)((const long long*)batch)[d];
    red_add_v4(&g_pool[g * 64 + c * 4], acc.x, acc.y, acc.z, acc.w);
    if (c == 0) atomicAdd(&g_cnt[g], 1.0f);
}

// ---------------- final MLP ----------------
__global__ void k_mlp(const float* __restrict__ Wl1, const float* __restrict__ bl1,
                      const float* __restrict__ Wl2, const float* __restrict__ bl2,
                      float* __restrict__ out) {
    __shared__ float mean[64];
    __shared__ float hid[32];
    int g = blockIdx.x;
    int t = threadIdx.x;
    float cnt = fmaxf(g_cnt[g], 1.0f);
    mean[t] = g_pool[g * 64 + t] / cnt;
    __syncthreads();
    if (t < 32) {
        float s = bl1[t];
        #pragma unroll 8
        for (int k = 0; k < 64; k++) s += mean[k] * Wl1[k * 32 + t];
        hid[t] = fmaxf(s, 0.0f);
    }
    __syncthreads();
    if (t < 9) {
        float s = bl2[t];
        #pragma unroll 8
        for (int k = 0; k < 32; k++) s += hid[k] * Wl2[k * 9 + t];
        out[g * 9 + t] = s;
    }
}

// ---------------- launch ----------------
extern "C" void kernel_launch(void* const* d_in, const int* in_sizes, int n_in,
                              void* d_out, int out_size) {
    const float* x     = (const float*)d_in[0];
    const void*  ei    = d_in[1];
    const void*  batch = d_in[2];
    const float* W1 = (const float*)d_in[3];  const float* b1 = (const float*)d_in[4];
    const float* W2 = (const float*)d_in[5];  const float* b2 = (const float*)d_in[6];
    const float* W3 = (const float*)d_in[7];  const float* b3 = (const float*)d_in[8];
    const float* W4 = (const float*)d_in[9];  const float* b4 = (const float*)d_in[10];
    const float* Wl1 = (const float*)d_in[11]; const float* bl1 = (const float*)d_in[12];
    const float* Wl2 = (const float*)d_in[13]; const float* bl2 = (const float*)d_in[14];
    float* out = (float*)d_out;

    __half *bufH, *bufX, *w2, *w3, *w4;
    cudaGetSymbolAddress((void**)&bufH, g_H);
    cudaGetSymbolAddress((void**)&bufX, g_X);
    cudaGetSymbolAddress((void**)&w2, g_W2);
    cudaGetSymbolAddress((void**)&w3, g_W3);
    cudaGetSymbolAddress((void**)&w4, g_W4);

    const int smemL1   = (128 * XSS + 128 * XSS) * 2 + 384 * 4 + 128 * 4;  // 71680
    const int smemAG128 = (128 * XSS + 128 * 136) * 2;                     // 69632
    const int smemAG64  = (128 * XSS + 128 * 72) * 2;                      // 53248
    cudaFuncSetAttribute((const void*)k_layer1,
                         cudaFuncAttributeMaxDynamicSharedMemorySize, smemL1);
    cudaFuncSetAttribute((const void*)k_agg_gemm<128>,
                         cudaFuncAttributeMaxDynamicSharedMemorySize, smemAG128);
    cudaFuncSetAttribute((const void*)k_agg_gemm<64>,
                         cudaFuncAttributeMaxDynamicSharedMemorySize, smemAG64);

    // preprocessing
    k_detect<<<1, 256>>>((const unsigned*)ei, (const unsigned*)batch);
    k_init<<<(NN + 255) / 256, 256>>>(W2, W3, W4);
    k_deg<<<NE / 256, 256>>>(ei);
    k_scan1<<<NB_SCAN, 512>>>();
    k_scan2<<<1, 256>>>();
    k_scan3<<<(NN + 255) / 256, 256>>>();
    k_build<<<NE / 256, 256>>>(ei);

    const int GTC = (NN + 127) / 128;   // 782

    // layer 1 fused: agg3 + gemm3 + X2@W2 -> H2 (g_H)
    k_layer1<<<GTC, 256, smemL1>>>(x, W1, b1, w2, bufH);
    // layer 2->3: X3 = relu(Â H2 + b2); H3 = X3@W3 -> g_X
    k_agg_gemm<128><<<GTC, 256, smemAG128>>>(bufH, b2, w3, bufX);
    // layer 3->4: X4 = relu(Â H3 + b3); H4 = X4@W4 -> g_H
    k_agg_gemm<64><<<GTC, 256, smemAG64>>>(bufX, b3, w4, bufH);
    // final agg + mean-pool
    k_agg64_pool<<<(NN * 16) / 256, 256>>>(bufH, b4, batch);

    k_mlp<<<NG, 64>>>(Wl1, bl1, Wl2, bl2, out);
}

// round 10
// speedup vs baseline: 1.2834x; 1.2834x over previous
#include <cuda_runtime.h>
#include <cuda_fp16.h>
#include <cstdint>
#include <math.h>

#define NN 100000
#define NE 1600000
#define NG 512
#define NB_SCAN 196   // ceil(NN/512)

// ---------------- device scratch (static, no allocations) ----------------
__device__ __align__(16) __half g_H[NN * 128];   // GEMM out (fp16)
__device__ __align__(16) __half g_X[NN * 128];   // activations (fp16)
__device__ __align__(16) float g_bufA[NN * 3];
__device__ __align__(16) __half g_W2[16384], g_W3[16384], g_W4[8192];
__device__ int   g_ideg[NN];
__device__ float g_dinv[NN];
__device__ __align__(16) int2  g_edge[NE];   // {src, norm bits}
__device__ int   g_rowptr[NN + 1];
__device__ int   g_cur[NN];
__device__ int   g_bsum[256];
__device__ __align__(16) float g_pool[NG * 64];
__device__ float g_cnt[NG];
__device__ int   g_e32;
__device__ int   g_b32;

// ---------------- helpers ----------------
__device__ __forceinline__ void red_add_v4(float* p, float a, float b, float c, float d) {
    asm volatile("red.global.add.v4.f32 [%0], {%1,%2,%3,%4};"
                 :: "l"(p), "f"(a), "f"(b), "f"(c), "f"(d) : "memory");
}
__device__ __forceinline__ uint32_t sptr(const void* p) {
    return (uint32_t)__cvta_generic_to_shared(p);
}
__device__ __forceinline__ void cp16(uint32_t dst, const void* src, bool valid) {
    int b = valid ? 16 : 0;
    asm volatile("cp.async.cg.shared.global [%0], [%1], 16, %2;"
                 :: "r"(dst), "l"(src), "r"(b));
}
__device__ __forceinline__ void cp_commit() {
    asm volatile("cp.async.commit_group;");
}
template<int N>
__device__ __forceinline__ void cp_wait() {
    asm volatile("cp.async.wait_group %0;" :: "n"(N));
}
__device__ __forceinline__ void ldsm_x4(uint32_t (&r)[4], uint32_t a) {
    asm volatile("ldmatrix.sync.aligned.m8n8.x4.shared.b16 {%0,%1,%2,%3}, [%4];"
                 : "=r"(r[0]), "=r"(r[1]), "=r"(r[2]), "=r"(r[3]) : "r"(a));
}
__device__ __forceinline__ void ldsm_x2t(uint32_t (&r)[2], uint32_t a) {
    asm volatile("ldmatrix.sync.aligned.m8n8.x2.trans.shared.b16 {%0,%1}, [%2];"
                 : "=r"(r[0]), "=r"(r[1]) : "r"(a));
}
__device__ __forceinline__ void mma_f16(float (&d)[4], const uint32_t (&a)[4],
                                        const uint32_t (&b)[2]) {
    asm volatile("mma.sync.aligned.m16n8k16.row.col.f32.f16.f16.f32 "
                 "{%0,%1,%2,%3}, {%4,%5,%6,%7}, {%8,%9}, {%0,%1,%2,%3};"
                 : "+f"(d[0]), "+f"(d[1]), "+f"(d[2]), "+f"(d[3])
                 : "r"(a[0]), "r"(a[1]), "r"(a[2]), "r"(a[3]), "r"(b[0]), "r"(b[1]));
}
__device__ __forceinline__ void acc_h4(float4& acc, uint2 u, float n) {
    float2 a = __half22float2(*(__half2*)&u.x);
    float2 b = __half22float2(*(__half2*)&u.y);
    acc.x += n * a.x; acc.y += n * a.y; acc.z += n * b.x; acc.w += n * b.y;
}

// ---------------- dtype detection (int32 vs int64 index arrays) ----------
__global__ void k_detect(const unsigned* __restrict__ e, const unsigned* __restrict__ b) {
    __shared__ unsigned se[256], sb[256];
    int t = threadIdx.x;
    unsigned ae = 0, ab = 0;
    const int SE = (2 * NE) / 4096;
    const int SB = NN / 4096;
    for (int i = t; i < 4096; i += 256) {
        ae |= e[(i * SE) | 1];
        ab |= b[(i * SB) | 1];
    }
    se[t] = ae; sb[t] = ab;
    __syncthreads();
    for (int s = 128; s; s >>= 1) {
        if (t < s) { se[t] |= se[t + s]; sb[t] |= sb[t + s]; }
        __syncthreads();
    }
    if (t == 0) { g_e32 = (se[0] != 0); g_b32 = (sb[0] != 0); }
}

// zero counters + convert weights (independent work, merged)
__global__ void k_init(const float* __restrict__ W2, const float* __restrict__ W3,
                       const float* __restrict__ W4) {
    int i = blockIdx.x * blockDim.x + threadIdx.x;
    if (i < NN) g_ideg[i] = 0;
    if (i < NG * 64) g_pool[i] = 0.0f;
    if (i < NG) g_cnt[i] = 0.0f;
    if (i < 16384)      g_W2[i] = __float2half_rn(W2[i]);
    else if (i < 32768) g_W3[i - 16384] = __float2half_rn(W3[i - 16384]);
    else if (i < 40960) g_W4[i - 32768] = __float2half_rn(W4[i - 32768]);
}

__global__ void k_deg(const void* __restrict__ ei) {
    int e = blockIdx.x * blockDim.x + threadIdx.x;
    if (e >= NE) return;
    int d;
    if (g_e32) d = ((const int*)ei)[NE + e];
    else       d = (int)((const long long*)ei)[NE + e];
    atomicAdd(&g_ideg[d], 1);
}

// ---------------- 2-level exclusive scan of degrees -> rowptr ------------
__global__ void k_scan1() {
    __shared__ int sm[512];
    int t = threadIdx.x;
    int i = blockIdx.x * 512 + t;
    int v = (i < NN) ? g_ideg[i] : 0;
    sm[t] = v;
    __syncthreads();
    for (int off = 1; off < 512; off <<= 1) {
        int x = 0;
        if (t >= off) x = sm[t - off];
        __syncthreads();
        if (t >= off) sm[t] += x;
        __syncthreads();
    }
    if (i < NN) g_rowptr[i] = sm[t] - v;
    if (t == 511) g_bsum[blockIdx.x] = sm[511];
}

__global__ void k_scan2() {
    __shared__ int sm[256];
    int t = threadIdx.x;
    int v = (t < NB_SCAN) ? g_bsum[t] : 0;
    sm[t] = v;
    __syncthreads();
    for (int off = 1; off < 256; off <<= 1) {
        int x = 0;
        if (t >= off) x = sm[t - off];
        __syncthreads();
        if (t >= off) sm[t] += x;
        __syncthreads();
    }
    if (t < NB_SCAN) g_bsum[t] = sm[t] - v;
}

__global__ void k_scan3() {
    int i = blockIdx.x * blockDim.x + threadIdx.x;
    if (i < NN) {
        int r = g_rowptr[i] + g_bsum[i >> 9];
        g_rowptr[i] = r;
        g_cur[i] = r;
        g_dinv[i] = rsqrtf((float)g_ideg[i] + 1.0f);
    }
    if (i == 0) g_rowptr[NN] = NE;
}

__global__ void k_build(const void* __restrict__ ei) {
    int e = blockIdx.x * blockDim.x + threadIdx.x;
    if (e >= NE) return;
    int s, d;
    if (g_e32) {
        const int* p = (const int*)ei;
        s = p[e]; d = p[NE + e];
    } else {
        const long long* p = (const long long*)ei;
        s = (int)p[e]; d = (int)p[NE + e];
    }
    int pos = atomicAdd(&g_cur[d], 1);
    g_edge[pos] = make_int2(s, __float_as_int(g_dinv[s] * g_dinv[d]));
}

// ---------------- layer-1 input aggregation: A = Â x (dim 3) -------------
__global__ void k_agg3(const float* __restrict__ x) {
    int d = blockIdx.x * blockDim.x + threadIdx.x;
    if (d >= NN) return;
    int p = g_rowptr[d], pe = g_rowptr[d + 1];
    float a0 = 0.f, a1 = 0.f, a2 = 0.f;
    for (; p + 2 <= pe; p += 2) {
        int2 e0 = g_edge[p], e1 = g_edge[p + 1];
        float n0 = __int_as_float(e0.y), n1 = __int_as_float(e1.y);
        a0 += n0 * x[e0.x * 3]     + n1 * x[e1.x * 3];
        a1 += n0 * x[e0.x * 3 + 1] + n1 * x[e1.x * 3 + 1];
        a2 += n0 * x[e0.x * 3 + 2] + n1 * x[e1.x * 3 + 2];
    }
    for (; p < pe; p++) {
        int2 e = g_edge[p]; float nm = __int_as_float(e.y);
        a0 += nm * x[e.x * 3]; a1 += nm * x[e.x * 3 + 1]; a2 += nm * x[e.x * 3 + 2];
    }
    float dv = g_dinv[d], sl = dv * dv;
    g_bufA[d * 3 + 0] = a0 + sl * x[d * 3 + 0];
    g_bufA[d * 3 + 1] = a1 + sl * x[d * 3 + 1];
    g_bufA[d * 3 + 2] = a2 + sl * x[d * 3 + 2];
}

// ---------------- layer-1 GEMM: X2 = relu(A @ W1 + b1) -> fp16 -----------
__global__ void k_gemm3(const float* __restrict__ X, const float* __restrict__ W,
                        const float* __restrict__ B) {
    __shared__ float Ws[3 * 128];
    __shared__ float xs[32 * 3];
    const int tx = threadIdx.x;
    const int ty = threadIdx.y;
    const int tid = ty * 32 + tx;
    const int row0 = blockIdx.x * 32;
    for (int i = tid; i < 3 * 128; i += 128) Ws[i] = W[i];
    if (tid < 96) xs[tid] = X[(size_t)row0 * 3 + tid];
    __syncthreads();

    float4 wv[3];
    #pragma unroll
    for (int k = 0; k < 3; k++) wv[k] = ((const float4*)Ws)[k * 32 + tx];
    float4 bv = ((const float4*)B)[tx];

    #pragma unroll
    for (int r = 0; r < 8; r++) {
        int row = row0 + ty * 8 + r;
        float x0 = xs[(ty * 8 + r) * 3], x1 = xs[(ty * 8 + r) * 3 + 1],
              x2 = xs[(ty * 8 + r) * 3 + 2];
        float4 h;
        h.x = fmaxf(x0 * wv[0].x + x1 * wv[1].x + x2 * wv[2].x + bv.x, 0.f);
        h.y = fmaxf(x0 * wv[0].y + x1 * wv[1].y + x2 * wv[2].y + bv.y, 0.f);
        h.z = fmaxf(x0 * wv[0].z + x1 * wv[1].z + x2 * wv[2].z + bv.z, 0.f);
        h.w = fmaxf(x0 * wv[0].w + x1 * wv[1].w + x2 * wv[2].w + bv.w, 0.f);
        uint2 o;
        *(__half2*)&o.x = __floats2half2_rn(h.x, h.y);
        *(__half2*)&o.y = __floats2half2_rn(h.z, h.w);
        *(uint2*)((__half*)g_X + (size_t)row * 128 + tx * 4) = o;
    }
}

// ---------------- tensor-core GEMM, cp.async 2-stage: H = X @ W ----------
template<int DOUT>
__global__ __launch_bounds__(256) void k_gemm_tc(
    const __half* __restrict__ X, const __half* __restrict__ W,
    __half* __restrict__ H) {
    constexpr int KT = 64;
    constexpr int XS = 72;
    constexpr int WS = DOUT + 8;
    constexpr int NW = DOUT / 2;
    constexpr int NF = NW / 8;
    constexpr int WU4 = DOUT / 8;
    constexpr int STAGE = 128 * XS + KT * WS;
    extern __shared__ __half smem[];

    const int tid = threadIdx.x;
    const int wid = tid >> 5;
    const int lane = tid & 31;
    const int warpM = wid & 3;
    const int warpN = wid >> 2;
    const int row0 = blockIdx.x * 128;

    auto load_stage = [&](int s, int k0) {
        __half* sX = smem + s * STAGE;
        __half* sW = sX + 128 * XS;
        #pragma unroll
        for (int i = tid; i < 128 * 8; i += 256) {
            int r = i >> 3, c = (i & 7) * 8;
            int gr = row0 + r;
            bool valid = gr < NN;
            int gsrc = valid ? gr : (NN - 1);
            cp16(sptr(sX + r * XS + c), X + (size_t)gsrc * 128 + k0 + c, valid);
        }
        #pragma unroll
        for (int i = tid; i < KT * WU4; i += 256) {
            int r = i / WU4, c = (i % WU4) * 8;
            cp16(sptr(sW + r * WS + c), W + (size_t)(k0 + r) * DOUT + c, true);
        }
        cp_commit();
    };

    float acc[2][NF][4];
    #pragma unroll
    for (int mi = 0; mi < 2; mi++)
        #pragma unroll
        for (int ni = 0; ni < NF; ni++)
            acc[mi][ni][0] = acc[mi][ni][1] = acc[mi][ni][2] = acc[mi][ni][3] = 0.f;

    load_stage(0, 0);
    load_stage(1, KT);

    #pragma unroll
    for (int it = 0; it < 2; it++) {
        if (it == 0) cp_wait<1>(); else cp_wait<0>();
        __syncthreads();
        __half* sX = smem + it * STAGE;
        __half* sW = sX + 128 * XS;
        #pragma unroll
        for (int kk = 0; kk < KT; kk += 16) {
            uint32_t a[2][4], b[NF][2];
            #pragma unroll
            for (int mi = 0; mi < 2; mi++) {
                int r = warpM * 32 + mi * 16 + (lane & 15);
                int c = kk + ((lane >> 4) << 3);
                ldsm_x4(a[mi], sptr(sX + r * XS + c));
            }
            #pragma unroll
            for (int ni = 0; ni < NF; ni++) {
                int r = kk + (lane & 15);
                int c = warpN * NW + ni * 8;
                ldsm_x2t(b[ni], sptr(sW + r * WS + c));
            }
            #pragma unroll
            for (int mi = 0; mi < 2; mi++)
                #pragma unroll
                for (int ni = 0; ni < NF; ni++)
                    mma_f16(acc[mi][ni], a[mi], b[ni]);
        }
    }

    #pragma unroll
    for (int mi = 0; mi < 2; mi++) {
        int r0 = row0 + warpM * 32 + mi * 16 + (lane >> 2);
        int c0 = warpN * NW + (lane & 3) * 2;
        #pragma unroll
        for (int ni = 0; ni < NF; ni++) {
            int c = c0 + ni * 8;
            if (r0 < NN) {
                __half2 h = __floats2half2_rn(acc[mi][ni][0], acc[mi][ni][1]);
                *(__half2*)(H + (size_t)r0 * DOUT + c) = h;
            }
            if (r0 + 8 < NN) {
                __half2 h = __floats2half2_rn(acc[mi][ni][2], acc[mi][ni][3]);
                *(__half2*)(H + (size_t)(r0 + 8) * DOUT + c) = h;
            }
        }
    }
}

// ---------------- CSR aggregation, dim 128 (fp16 gather, f32 accum) ------
__global__ void k_agg128(const __half* __restrict__ H, const float* __restrict__ B) {
    int warp = (blockIdx.x * blockDim.x + threadIdx.x) >> 5;
    int lane = threadIdx.x & 31;
    if (warp >= NN) return;
    int d = warp;
    const uint2* H2 = (const uint2*)H;
    int p = g_rowptr[d], pe = g_rowptr[d + 1];
    float4 acc = make_float4(0.f, 0.f, 0.f, 0.f);
    // peel to even p (int4 loads cover 2 edges, need 16B alignment)
    if (p < pe && (p & 1)) {
        int2 e = g_edge[p];
        acc_h4(acc, H2[(size_t)e.x * 32 + lane], __int_as_float(e.y));
        p++;
    }
    for (; p + 8 <= pe; p += 8) {
        int4 a0 = *(const int4*)&g_edge[p];
        int4 a1 = *(const int4*)&g_edge[p + 2];
        int4 a2 = *(const int4*)&g_edge[p + 4];
        int4 a3 = *(const int4*)&g_edge[p + 6];
        uint2 u0 = H2[(size_t)a0.x * 32 + lane];
        uint2 u1 = H2[(size_t)a0.z * 32 + lane];
        uint2 u2 = H2[(size_t)a1.x * 32 + lane];
        uint2 u3 = H2[(size_t)a1.z * 32 + lane];
        uint2 u4 = H2[(size_t)a2.x * 32 + lane];
        uint2 u5 = H2[(size_t)a2.z * 32 + lane];
        uint2 u6 = H2[(size_t)a3.x * 32 + lane];
        uint2 u7 = H2[(size_t)a3.z * 32 + lane];
        acc_h4(acc, u0, __int_as_float(a0.y)); acc_h4(acc, u1, __int_as_float(a0.w));
        acc_h4(acc, u2, __int_as_float(a1.y)); acc_h4(acc, u3, __int_as_float(a1.w));
        acc_h4(acc, u4, __int_as_float(a2.y)); acc_h4(acc, u5, __int_as_float(a2.w));
        acc_h4(acc, u6, __int_as_float(a3.y)); acc_h4(acc, u7, __int_as_float(a3.w));
    }
    for (; p + 2 <= pe; p += 2) {
        int4 a0 = *(const int4*)&g_edge[p];
        uint2 u0 = H2[(size_t)a0.x * 32 + lane];
        uint2 u1 = H2[(size_t)a0.z * 32 + lane];
        acc_h4(acc, u0, __int_as_float(a0.y));
        acc_h4(acc, u1, __int_as_float(a0.w));
    }
    if (p < pe) {
        int2 e = g_edge[p];
        acc_h4(acc, H2[(size_t)e.x * 32 + lane], __int_as_float(e.y));
    }

    float dv = g_dinv[d], sl = dv * dv;
    acc_h4(acc, H2[(size_t)d * 32 + lane], sl);
    float4 bv = ((const float4*)B)[lane];
    acc.x = fmaxf(acc.x + bv.x, 0.f);
    acc.y = fmaxf(acc.y + bv.y, 0.f);
    acc.z = fmaxf(acc.z + bv.z, 0.f);
    acc.w = fmaxf(acc.w + bv.w, 0.f);
    uint2 o;
    *(__half2*)&o.x = __floats2half2_rn(acc.x, acc.y);
    *(__half2*)&o.y = __floats2half2_rn(acc.z, acc.w);
    *(uint2*)((__half*)g_X + (size_t)d * 128 + lane * 4) = o;
}

// ---------------- final agg (dim 64, fp16 gather) + mean-pool scatter ----
__global__ void k_agg64_pool(const __half* __restrict__ H, const float* __restrict__ B,
                             const void* __restrict__ batch) {
    int gt = blockIdx.x * blockDim.x + threadIdx.x;
    int d = gt >> 4;
    int c = gt & 15;
    if (d >= NN) return;
    const uint2* H2 = (const uint2*)H;
    int p = g_rowptr[d], pe = g_rowptr[d + 1];
    float4 acc = make_float4(0.f, 0.f, 0.f, 0.f);
    if (p < pe && (p & 1)) {
        int2 e = g_edge[p];
        acc_h4(acc, H2[(size_t)e.x * 16 + c], __int_as_float(e.y));
        p++;
    }
    for (; p + 8 <= pe; p += 8) {
        int4 a0 = *(const int4*)&g_edge[p];
        int4 a1 = *(const int4*)&g_edge[p + 2];
        int4 a2 = *(const int4*)&g_edge[p + 4];
        int4 a3 = *(const int4*)&g_edge[p + 6];
        uint2 u0 = H2[(size_t)a0.x * 16 + c];
        uint2 u1 = H2[(size_t)a0.z * 16 + c];
        uint2 u2 = H2[(size_t)a1.x * 16 + c];
        uint2 u3 = H2[(size_t)a1.z * 16 + c];
        uint2 u4 = H2[(size_t)a2.x * 16 + c];
        uint2 u5 = H2[(size_t)a2.z * 16 + c];
        uint2 u6 = H2[(size_t)a3.x * 16 + c];
        uint2 u7 = H2[(size_t)a3.z * 16 + c];
        acc_h4(acc, u0, __int_as_float(a0.y)); acc_h4(acc, u1, __int_as_float(a0.w));
        acc_h4(acc, u2, __int_as_float(a1.y)); acc_h4(acc, u3, __int_as_float(a1.w));
        acc_h4(acc, u4, __int_as_float(a2.y)); acc_h4(acc, u5, __int_as_float(a2.w));
        acc_h4(acc, u6, __int_as_float(a3.y)); acc_h4(acc, u7, __int_as_float(a3.w));
    }
    for (; p + 2 <= pe; p += 2) {
        int4 a0 = *(const int4*)&g_edge[p];
        uint2 u0 = H2[(size_t)a0.x * 16 + c];
        uint2 u1 = H2[(size_t)a0.z * 16 + c];
        acc_h4(acc, u0, __int_as_float(a0.y));
        acc_h4(acc, u1, __int_as_float(a0.w));
    }
    if (p < pe) {
        int2 e = g_edge[p];
        acc_h4(acc, H2[(size_t)e.x * 16 + c], __int_as_float(e.y));
    }

    float dv = g_dinv[d], sl = dv * dv;
    acc_h4(acc, H2[(size_t)d * 16 + c], sl);
    float4 bv = ((const float4*)B)[c];
    acc.x += bv.x; acc.y += bv.y; acc.z += bv.z; acc.w += bv.w;
    int g;
    if (g_b32) g = ((const int*)batch)[d];
    else       g = (int)((const long long*)batch)[d];
    red_add_v4(&g_pool[g * 64 + c * 4], acc.x, acc.y, acc.z, acc.w);
    if (c == 0) atomicAdd(&g_cnt[g], 1.0f);
}

// ---------------- final MLP ----------------
__global__ void k_mlp(const float* __restrict__ Wl1, const float* __restrict__ bl1,
                      const float* __restrict__ Wl2, const float* __restrict__ bl2,
                      float* __restrict__ out) {
    __shared__ float mean[64];
    __shared__ float hid[32];
    int g = blockIdx.x;
    int t = threadIdx.x;
    float cnt = fmaxf(g_cnt[g], 1.0f);
    mean[t] = g_pool[g * 64 + t] / cnt;
    __syncthreads();
    if (t < 32) {
        float s = bl1[t];
        #pragma unroll 8
        for (int k = 0; k < 64; k++) s += mean[k] * Wl1[k * 32 + t];
        hid[t] = fmaxf(s, 0.0f);
    }
    __syncthreads();
    if (t < 9) {
        float s = bl2[t];
        #pragma unroll 8
        for (int k = 0; k < 32; k++) s += hid[k] * Wl2[k * 9 + t];
        out[g * 9 + t] = s;
    }
}

// ---------------- launch ----------------
extern "C" void kernel_launch(void* const* d_in, const int* in_sizes, int n_in,
                              void* d_out, int out_size) {
    const float* x     = (const float*)d_in[0];
    const void*  ei    = d_in[1];
    const void*  batch = d_in[2];
    const float* W1 = (const float*)d_in[3];  const float* b1 = (const float*)d_in[4];
    const float* W2 = (const float*)d_in[5];  const float* b2 = (const float*)d_in[6];
    const float* W3 = (const float*)d_in[7];  const float* b3 = (const float*)d_in[8];
    const float* W4 = (const float*)d_in[9];  const float* b4 = (const float*)d_in[10];
    const float* Wl1 = (const float*)d_in[11]; const float* bl1 = (const float*)d_in[12];
    const float* Wl2 = (const float*)d_in[13]; const float* bl2 = (const float*)d_in[14];
    float* out = (float*)d_out;

    float* bufA;
    __half *bufH, *bufX, *w2, *w3, *w4;
    cudaGetSymbolAddress((void**)&bufH, g_H);
    cudaGetSymbolAddress((void**)&bufX, g_X);
    cudaGetSymbolAddress((void**)&bufA, g_bufA);
    cudaGetSymbolAddress((void**)&w2, g_W2);
    cudaGetSymbolAddress((void**)&w3, g_W3);
    cudaGetSymbolAddress((void**)&w4, g_W4);

    const int smem128 = 2 * (128 * 72 + 64 * 136) * 2;   // 71680
    const int smem64  = 2 * (128 * 72 + 64 * 72) * 2;    // 55296
    cudaFuncSetAttribute((const void*)k_gemm_tc<128>,
                         cudaFuncAttributeMaxDynamicSharedMemorySize, smem128);
    cudaFuncSetAttribute((const void*)k_gemm_tc<64>,
                         cudaFuncAttributeMaxDynamicSharedMemorySize, smem64);

    // preprocessing
    k_detect<<<1, 256>>>((const unsigned*)ei, (const unsigned*)batch);
    k_init<<<(NN + 255) / 256, 256>>>(W2, W3, W4);
    k_deg<<<NE / 256, 256>>>(ei);
    k_scan1<<<NB_SCAN, 512>>>();
    k_scan2<<<1, 256>>>();
    k_scan3<<<(NN + 255) / 256, 256>>>();
    k_build<<<NE / 256, 256>>>(ei);

    const int GTC = (NN + 127) / 128;   // 782

    // layer 1: A = Â x (dim 3), X2 = relu(A @ W1 + b1) -> fp16
    k_agg3<<<(NN + 255) / 256, 256>>>(x);
    k_gemm3<<<NN / 32, dim3(32, 4)>>>(bufA, W1, b1);

    // layer 2
    k_gemm_tc<128><<<GTC, 256, smem128>>>(bufX, w2, bufH);
    k_agg128<<<12500, 256>>>(bufH, b2);
    // layer 3
    k_gemm_tc<128><<<GTC, 256, smem128>>>(bufX, w3, bufH);
    k_agg128<<<12500, 256>>>(bufH, b3);
    // layer 4
    k_gemm_tc<64><<<GTC, 256, smem64>>>(bufX, w4, bufH);
    k_agg64_pool<<<(NN * 16) / 256, 256>>>(bufH, b4, batch);

    k_mlp<<<NG, 64>>>(Wl1, bl1, Wl2, bl2, out);
}